// round 3
// baseline (speedup 1.0000x reference)
#include <cuda_runtime.h>

#define CN    64
#define HH    256
#define HWSZ  65536
#define NCLS  6
#define NWIN  1024

// ---------------- scratch (device globals; no allocations allowed) ----------
__device__ float g_mask[NCLS * NWIN * 64];
__device__ float g_good[NCLS * NWIN * 64];
__device__ float g_out1[(size_t)NCLS * CN * HWSZ];   // x + class_attn
__device__ float g_x112[(size_t)NCLS * CN * HWSZ];
__device__ float g_x223[(size_t)NCLS * CN * HWSZ];

// ---------------------------------------------------------------------------
// K1: per-(class, window) mask = mean over (heads, q) of dots.
// dots = (q.k)*0.25 + relbias  ->  mask[k] = 0.25/256 * sum_ch qsum[ch]*k[ch][k]
//                                   + (1/256) * sum_{q,h} relbias[idx(q,k),h]
// ---------------------------------------------------------------------------
__global__ __launch_bounds__(256)
void k_mask(const float* __restrict__ x, const float* __restrict__ qkw,
            const float* __restrict__ qks, const float* __restrict__ qkb,
            const float* __restrict__ relb) {
    int cls = blockIdx.y, win = blockIdx.x;
    int wy = win >> 5, wx = win & 31;
    extern __shared__ float sm[];
    float* xw   = sm;            // 64*64         = 4096
    float* wsm  = xw + 4096;     // 128*65 padded = 8320
    float* qk   = wsm + 8320;    // 128*65 padded = 8320
    float* qsum = qk + 8320;     // 64
    float* rsm  = qsum + 64;     // 900
    int tid = threadIdx.x;
    const float* xb = x + ((size_t)cls * CN) * HWSZ;

    for (int id = tid; id < 512; id += 256) {
        int ch = id >> 3, i = id & 7;
        const float* p = xb + (size_t)ch * HWSZ + (wy * 8 + i) * HH + wx * 8;
        float4 a = *(const float4*)p;
        float4 b = *(const float4*)(p + 4);
        float* d = xw + ch * 64 + i * 8;
        d[0]=a.x; d[1]=a.y; d[2]=a.z; d[3]=a.w;
        d[4]=b.x; d[5]=b.y; d[6]=b.z; d[7]=b.w;
    }
    const float* wb = qkw + (size_t)cls * 8192;
    for (int id = tid; id < 8192; id += 256)
        wsm[(id >> 6) * 65 + (id & 63)] = wb[id];
    const float* rb = relb + cls * 900;
    for (int id = tid; id < 900; id += 256) rsm[id] = rb[id];
    __syncthreads();

    const float* sS = qks + cls * 128;
    const float* sB = qkb + cls * 128;
    for (int idx = tid; idx < 4096; idx += 256) {
        int pp = idx >> 7, oc = idx & 127;
        int p0 = pp * 2;
        float a0 = 0.f, a1 = 0.f;
        const float* wr = wsm + oc * 65;
        const float* xr = xw + p0;
        #pragma unroll 16
        for (int c = 0; c < 64; c++) {
            float w = wr[c];
            a0 += w * xr[c * 64];
            a1 += w * xr[c * 64 + 1];
        }
        float s = sS[oc], b = sB[oc];
        qk[oc * 65 + p0]     = fmaxf(a0 * s + b, 0.f);
        qk[oc * 65 + p0 + 1] = fmaxf(a1 * s + b, 0.f);
    }
    __syncthreads();

    if (tid < 64) {
        float s = 0.f;
        const float* r = qk + tid * 65;
        #pragma unroll 16
        for (int p = 0; p < 64; p++) s += r[p];
        qsum[tid] = s;
    }
    __syncthreads();

    if (tid < 64) {
        int kp = tid, ik = kp >> 3, jk = kp & 7;
        float dot = 0.f;
        #pragma unroll 16
        for (int ch = 0; ch < 64; ch++) dot += qsum[ch] * qk[(64 + ch) * 65 + kp];
        float rbv = 0.f;
        for (int q = 0; q < 64; q++) {
            int ridx = ((q >> 3) - ik + 7) * 15 + ((q & 7) - jk + 7);
            const float* r4 = rsm + ridx * 4;
            rbv += r4[0] + r4[1] + r4[2] + r4[3];
        }
        g_mask[(cls * NWIN + win) * 64 + kp] = dot * (0.25f / 256.f) + rbv * (1.f / 256.f);
    }
}

// ---------------------------------------------------------------------------
// K2: good = (mask == max over classes) ? 1 : -1
// ---------------------------------------------------------------------------
__global__ void k_good() {
    int i = blockIdx.x * 256 + threadIdx.x;   // 65536 total
    float m[NCLS], mx = -1e30f;
    #pragma unroll
    for (int c = 0; c < NCLS; c++) {
        m[c] = g_mask[c * NWIN * 64 + i];
        mx = fmaxf(mx, m[c]);
    }
    #pragma unroll
    for (int c = 0; c < NCLS; c++)
        g_good[c * NWIN * 64 + i] = (m[c] == mx) ? 1.f : -1.f;
}

// ---------------------------------------------------------------------------
// K3: fused windowed attention: q/k/v 1x1 convs, dots+bias, softmax,
//     +/-1 cross-class mask, attn@v, residual, un-window.
// ---------------------------------------------------------------------------
__global__ __launch_bounds__(256)
void k_attn(const float* __restrict__ x, const float* __restrict__ qkw,
            const float* __restrict__ qks, const float* __restrict__ qkb,
            const float* __restrict__ relb, const float* __restrict__ wvw,
            const float* __restrict__ wvs, const float* __restrict__ wvb) {
    int cls = blockIdx.y, win = blockIdx.x;
    int wy = win >> 5, wx = win & 31;
    extern __shared__ float sm[];
    float* xw  = sm;             // 4096
    float* wsm = xw + 4096;      // 8320 (128*65)
    float* qsm = wsm + 8320;     // 4160 (64*65)
    float* ksm = qsm + 4160;     // 4096  [h][kp][d]
    float* vsm = ksm + 4096;     // 4096  [h][kp][d]
    float* rsm = vsm + 4096;     // 900
    float* gsm = rsm + 900;      // 64
    float* osm = gsm + 64;       // 4096
    int tid = threadIdx.x;
    const float* xb = x + ((size_t)cls * CN) * HWSZ;

    for (int id = tid; id < 512; id += 256) {
        int ch = id >> 3, i = id & 7;
        const float* p = xb + (size_t)ch * HWSZ + (wy * 8 + i) * HH + wx * 8;
        float4 a = *(const float4*)p;
        float4 b = *(const float4*)(p + 4);
        float* d = xw + ch * 64 + i * 8;
        d[0]=a.x; d[1]=a.y; d[2]=a.z; d[3]=a.w;
        d[4]=b.x; d[5]=b.y; d[6]=b.z; d[7]=b.w;
    }
    const float* wb = qkw + (size_t)cls * 8192;
    for (int id = tid; id < 8192; id += 256)
        wsm[(id >> 6) * 65 + (id & 63)] = wb[id];
    const float* rb = relb + cls * 900;
    for (int id = tid; id < 900; id += 256) rsm[id] = rb[id];
    if (tid < 64) gsm[tid] = g_good[(cls * NWIN + win) * 64 + tid];
    __syncthreads();

    // q (oc<64) and k (oc>=64) 1x1 conv-bn-relu
    const float* sS = qks + cls * 128;
    const float* sB = qkb + cls * 128;
    for (int idx = tid; idx < 4096; idx += 256) {
        int pp = idx >> 7, oc = idx & 127;
        int p0 = pp * 2;
        float a0 = 0.f, a1 = 0.f;
        const float* wr = wsm + oc * 65;
        const float* xr = xw + p0;
        #pragma unroll 16
        for (int c = 0; c < 64; c++) {
            float w = wr[c];
            a0 += w * xr[c * 64];
            a1 += w * xr[c * 64 + 1];
        }
        float s = sS[oc], b = sB[oc];
        float v0 = fmaxf(a0 * s + b, 0.f);
        float v1 = fmaxf(a1 * s + b, 0.f);
        if (oc < 64) {
            qsm[oc * 65 + p0] = v0;
            qsm[oc * 65 + p0 + 1] = v1;
        } else {
            int cc = oc - 64, h = cc >> 4, d = cc & 15;
            ksm[h * 1024 + p0 * 16 + d] = v0;
            ksm[h * 1024 + (p0 + 1) * 16 + d] = v1;
        }
    }
    __syncthreads();

    // v conv (reuse wsm)
    const float* wvb2 = wvw + (size_t)cls * 4096;
    for (int id = tid; id < 4096; id += 256)
        wsm[(id >> 6) * 65 + (id & 63)] = wvb2[id];
    __syncthreads();
    const float* vS = wvs + cls * 64;
    const float* vB = wvb + cls * 64;
    for (int idx = tid; idx < 2048; idx += 256) {
        int pp = idx >> 6, oc = idx & 63;
        int p0 = pp * 2;
        float a0 = 0.f, a1 = 0.f;
        const float* wr = wsm + oc * 65;
        const float* xr = xw + p0;
        #pragma unroll 16
        for (int c = 0; c < 64; c++) {
            float w = wr[c];
            a0 += w * xr[c * 64];
            a1 += w * xr[c * 64 + 1];
        }
        float s = vS[oc], b = vB[oc];
        int h = oc >> 4, d = oc & 15;
        vsm[h * 1024 + p0 * 16 + d]       = fmaxf(a0 * s + b, 0.f);
        vsm[h * 1024 + (p0 + 1) * 16 + d] = fmaxf(a1 * s + b, 0.f);
    }
    __syncthreads();

    // attention: thread = (head, query-pos)
    int h = tid >> 6, qp = tid & 63;
    int iq = qp >> 3, jq = qp & 7;
    float qreg[16];
    #pragma unroll
    for (int d = 0; d < 16; d++) qreg[d] = qsm[(h * 16 + d) * 65 + qp];

    float a[64];
    const float* kb2 = ksm + h * 1024;
    #pragma unroll
    for (int kp = 0; kp < 64; kp++) {
        const float* kr = kb2 + kp * 16;
        float dot = 0.f;
        #pragma unroll
        for (int d = 0; d < 16; d++) dot += qreg[d] * kr[d];
        int ridx = (iq - (kp >> 3) + 7) * 15 + (jq - (kp & 7) + 7);
        a[kp] = dot * 0.25f + rsm[ridx * 4 + h];
    }
    float mx = -1e30f;
    #pragma unroll
    for (int kp = 0; kp < 64; kp++) mx = fmaxf(mx, a[kp]);
    float ssum = 0.f;
    #pragma unroll
    for (int kp = 0; kp < 64; kp++) { a[kp] = __expf(a[kp] - mx); ssum += a[kp]; }
    float gq = gsm[qp] / ssum;

    float o[16];
    #pragma unroll
    for (int d = 0; d < 16; d++) o[d] = 0.f;
    const float* vb3 = vsm + h * 1024;
    #pragma unroll
    for (int kp = 0; kp < 64; kp++) {
        float w = a[kp] * gq * gsm[kp];
        const float* vr = vb3 + kp * 16;
        #pragma unroll
        for (int d = 0; d < 16; d++) o[d] += w * vr[d];
    }
    #pragma unroll
    for (int d = 0; d < 16; d++)
        osm[(h * 16 + d) * 64 + qp] = o[d] + xw[(h * 16 + d) * 64 + qp];
    __syncthreads();

    float* ob = g_out1 + ((size_t)cls * CN) * HWSZ;
    for (int id = tid; id < 512; id += 256) {
        int ch = id >> 3, i = id & 7;
        const float* src = osm + ch * 64 + i * 8;
        float4 a4 = {src[0], src[1], src[2], src[3]};
        float4 b4 = {src[4], src[5], src[6], src[7]};
        float* p = ob + (size_t)ch * HWSZ + (wy * 8 + i) * HH + wx * 8;
        *(float4*)p = a4;
        *(float4*)(p + 4) = b4;
    }
}

// ---------------------------------------------------------------------------
// K4: sum of M conv3x3-BN-relu6. Tile 16x4, thread = (oc, row). Weights staged
//     per 8-channel chunk with odd stride (conflict-free), input reads are
//     warp-uniform broadcasts.
// ---------------------------------------------------------------------------
template <int M>
__global__ __launch_bounds__(256)
void k_conv3(int src_id, int dst_id,
             const float* __restrict__ w, const float* __restrict__ s,
             const float* __restrict__ b, int m0) {
    int cls = blockIdx.z;
    int tx0 = blockIdx.x * 16, ty0 = blockIdx.y * 4;
    const float* src = (src_id == 0 ? g_out1 : g_x112) + (size_t)cls * CN * HWSZ;
    float* dst = (dst_id == 1 ? g_x112 : g_x223) + (size_t)cls * CN * HWSZ;
    extern __shared__ float sm[];
    float* ism = sm;            // 64*6*18 = 6912
    float* wsm = ism + 6912;    // M*64*73
    int tid = threadIdx.x;
    int oc = tid & 63, grp = tid >> 6;

    for (int id = tid; id < 6912; id += 256) {
        int c = id / 108, rem = id - c * 108;
        int r = rem / 18, col = rem - r * 18;
        int gy = ty0 + r - 1, gx = tx0 + col - 1;
        float v = 0.f;
        if ((unsigned)gy < 256u && (unsigned)gx < 256u)
            v = src[(size_t)c * HWSZ + gy * HH + gx];
        ism[id] = v;
    }
    const float* wbase = w + ((size_t)cls * 6 + m0) * 36864;
    float acc[M][16];
    #pragma unroll
    for (int m = 0; m < M; m++)
        #pragma unroll
        for (int xx = 0; xx < 16; xx++) acc[m][xx] = 0.f;

    for (int cc = 0; cc < 64; cc += 8) {
        __syncthreads();
        for (int id = tid; id < M * 64 * 72; id += 256) {
            int mo = id / 72, i = id - mo * 72;
            wsm[mo * 73 + i] = wbase[mo * 576 + cc * 9 + i];
        }
        __syncthreads();
        for (int c = 0; c < 8; c++) {
            const float* ib = ism + (cc + c) * 108 + grp * 18;
            #pragma unroll
            for (int ky = 0; ky < 3; ky++) {
                float r_[18];
                const float* ir = ib + ky * 18;
                #pragma unroll
                for (int j = 0; j < 18; j++) r_[j] = ir[j];
                #pragma unroll
                for (int m = 0; m < M; m++) {
                    const float* wp = wsm + (m * 64 + oc) * 73 + c * 9 + ky * 3;
                    float w0 = wp[0], w1 = wp[1], w2 = wp[2];
                    #pragma unroll
                    for (int xx = 0; xx < 16; xx++)
                        acc[m][xx] += w0 * r_[xx] + w1 * r_[xx + 1] + w2 * r_[xx + 2];
                }
            }
        }
    }

    float res[16];
    #pragma unroll
    for (int xx = 0; xx < 16; xx++) res[xx] = 0.f;
    #pragma unroll
    for (int m = 0; m < M; m++) {
        float sv = s[((size_t)cls * 6 + m0 + m) * 64 + oc];
        float bv = b[((size_t)cls * 6 + m0 + m) * 64 + oc];
        #pragma unroll
        for (int xx = 0; xx < 16; xx++) {
            float v = acc[m][xx] * sv + bv;
            res[xx] += fminf(fmaxf(v, 0.f), 6.f);
        }
    }
    __syncthreads();
    float* osm = wsm;   // reuse (>= 64*65 floats)
    #pragma unroll
    for (int xx = 0; xx < 16; xx++) osm[oc * 65 + grp * 16 + xx] = res[xx];
    __syncthreads();
    for (int id = tid; id < 1024; id += 256) {
        int oc2 = id >> 4, rq = id & 15, r = rq >> 2, qx = rq & 3;
        const float* sp = osm + oc2 * 65 + r * 16 + qx * 4;
        float4 v = {sp[0], sp[1], sp[2], sp[3]};
        *(float4*)(dst + (size_t)oc2 * HWSZ + (ty0 + r) * HH + tx0 + qx * 4) = v;
    }
}

// ---------------------------------------------------------------------------
// K5: x33 = conv3x3(x223) fused with concat 1x1-BN + residual + relu.
// ---------------------------------------------------------------------------
__global__ __launch_bounds__(256)
void k_final(const float* __restrict__ w, const float* __restrict__ s,
             const float* __restrict__ b,
             const float* __restrict__ catw, const float* __restrict__ cats,
             const float* __restrict__ catb, float* __restrict__ out) {
    int cls = blockIdx.z;
    int tx0 = blockIdx.x * 16, ty0 = blockIdx.y * 4;
    const float* src  = g_x223 + (size_t)cls * CN * HWSZ;
    const float* x112 = g_x112 + (size_t)cls * CN * HWSZ;
    const float* out1 = g_out1 + (size_t)cls * CN * HWSZ;
    extern __shared__ float sm[];
    float* ism  = sm;              // 6912   (x223 tile + halo)
    float* wsm  = ism + 6912;      // 64*73 = 4672
    float* cwsm = wsm + 4672;      // 64*193 = 12352
    float* x1sm = cwsm + 12352;    // 4096
    float* x3sm = x1sm + 4096;     // 64*65 = 4160
    float* osm  = x3sm + 4160;     // 64*65 = 4160
    int tid = threadIdx.x;
    int oc = tid & 63, grp = tid >> 6;

    for (int id = tid; id < 6912; id += 256) {
        int c = id / 108, rem = id - c * 108;
        int r = rem / 18, col = rem - r * 18;
        int gy = ty0 + r - 1, gx = tx0 + col - 1;
        float v = 0.f;
        if ((unsigned)gy < 256u && (unsigned)gx < 256u)
            v = src[(size_t)c * HWSZ + gy * HH + gx];
        ism[id] = v;
    }
    for (int id = tid; id < 4096; id += 256) {
        int c = id >> 6, px = id & 63, r = px >> 4, col = px & 15;
        x1sm[id] = x112[(size_t)c * HWSZ + (ty0 + r) * HH + tx0 + col];
    }
    const float* cwb = catw + (size_t)cls * 64 * 192;
    for (int id = tid; id < 64 * 192; id += 256) {
        int o2 = id / 192, c2 = id - o2 * 192;
        cwsm[o2 * 193 + c2] = cwb[id];
    }
    const float* wbase = w + ((size_t)cls * 6 + 5) * 36864;
    float acc[16];
    #pragma unroll
    for (int xx = 0; xx < 16; xx++) acc[xx] = 0.f;

    for (int cc = 0; cc < 64; cc += 8) {
        __syncthreads();
        for (int id = tid; id < 64 * 72; id += 256) {
            int mo = id / 72, i = id - mo * 72;
            wsm[mo * 73 + i] = wbase[mo * 576 + cc * 9 + i];
        }
        __syncthreads();
        for (int c = 0; c < 8; c++) {
            const float* ib = ism + (cc + c) * 108 + grp * 18;
            #pragma unroll
            for (int ky = 0; ky < 3; ky++) {
                float r_[18];
                const float* ir = ib + ky * 18;
                #pragma unroll
                for (int j = 0; j < 18; j++) r_[j] = ir[j];
                const float* wp = wsm + oc * 73 + c * 9 + ky * 3;
                float w0 = wp[0], w1 = wp[1], w2 = wp[2];
                #pragma unroll
                for (int xx = 0; xx < 16; xx++)
                    acc[xx] += w0 * r_[xx] + w1 * r_[xx + 1] + w2 * r_[xx + 2];
            }
        }
    }
    float sv = s[((size_t)cls * 6 + 5) * 64 + oc];
    float bv = b[((size_t)cls * 6 + 5) * 64 + oc];
    #pragma unroll
    for (int xx = 0; xx < 16; xx++) {
        float v = acc[xx] * sv + bv;
        x3sm[oc * 65 + grp * 16 + xx] = fminf(fmaxf(v, 0.f), 6.f);
    }
    __syncthreads();

    // 1x1 over [x112, x223, x33]
    float y[16];
    #pragma unroll
    for (int xx = 0; xx < 16; xx++) y[xx] = 0.f;
    const float* cw = cwsm + oc * 193;
    for (int c = 0; c < 64; c++) {
        float w1 = cw[c], w2 = cw[64 + c], w3 = cw[128 + c];
        const float* p1 = x1sm + c * 64 + grp * 16;
        const float* p2 = ism + c * 108 + (grp + 1) * 18 + 1;
        const float* p3 = x3sm + c * 65 + grp * 16;
        #pragma unroll
        for (int xx = 0; xx < 16; xx++)
            y[xx] += w1 * p1[xx] + w2 * p2[xx] + w3 * p3[xx];
    }
    float csv = cats[cls * 64 + oc], cbv = catb[cls * 64 + oc];
    #pragma unroll
    for (int xx = 0; xx < 16; xx++)
        osm[oc * 65 + grp * 16 + xx] = y[xx] * csv + cbv;
    __syncthreads();

    float* ob = out + ((size_t)cls * CN) * HWSZ;
    for (int id = tid; id < 1024; id += 256) {
        int oc2 = id >> 4, rq = id & 15, r = rq >> 2, qx = rq & 3;
        const float* sp = osm + oc2 * 65 + r * 16 + qx * 4;
        const float* rp = out1 + (size_t)oc2 * HWSZ + (ty0 + r) * HH + tx0 + qx * 4;
        float4 rv = *(const float4*)rp;
        float4 v;
        v.x = fmaxf(sp[0] + rv.x, 0.f);
        v.y = fmaxf(sp[1] + rv.y, 0.f);
        v.z = fmaxf(sp[2] + rv.z, 0.f);
        v.w = fmaxf(sp[3] + rv.w, 0.f);
        *(float4*)(ob + (size_t)oc2 * HWSZ + (ty0 + r) * HH + tx0 + qx * 4) = v;
    }
}

// ---------------------------------------------------------------------------
extern "C" void kernel_launch(void* const* d_in, const int* in_sizes, int n_in,
                              void* d_out, int out_size) {
    const float* x    = (const float*)d_in[0];
    const float* qkw  = (const float*)d_in[1];
    const float* qks  = (const float*)d_in[2];
    const float* qkb  = (const float*)d_in[3];
    const float* relb = (const float*)d_in[4];
    const float* wvw  = (const float*)d_in[5];
    const float* wvs  = (const float*)d_in[6];
    const float* wvb  = (const float*)d_in[7];
    const float* mmsw = (const float*)d_in[8];
    const float* mmss = (const float*)d_in[9];
    const float* mmsb = (const float*)d_in[10];
    const float* catw = (const float*)d_in[11];
    const float* cats = (const float*)d_in[12];
    const float* catb = (const float*)d_in[13];
    float* out = (float*)d_out;

    const int SM_MASK  = 21700 * 4;   // 86800
    const int SM_ATTN  = 29828 * 4;   // 119312
    const int SM_C3    = (6912 + 3 * 64 * 73) * 4;   // 83712
    const int SM_C2    = (6912 + 2 * 64 * 73) * 4;   // 65024
    const int SM_FIN   = (6912 + 4672 + 12352 + 4096 + 4160 + 4160) * 4; // 145408

    cudaFuncSetAttribute(k_mask,     cudaFuncAttributeMaxDynamicSharedMemorySize, SM_MASK);
    cudaFuncSetAttribute(k_attn,     cudaFuncAttributeMaxDynamicSharedMemorySize, SM_ATTN);
    cudaFuncSetAttribute(k_conv3<3>, cudaFuncAttributeMaxDynamicSharedMemorySize, SM_C3);
    cudaFuncSetAttribute(k_conv3<2>, cudaFuncAttributeMaxDynamicSharedMemorySize, SM_C2);
    cudaFuncSetAttribute(k_final,    cudaFuncAttributeMaxDynamicSharedMemorySize, SM_FIN);

    k_mask<<<dim3(NWIN, NCLS), 256, SM_MASK>>>(x, qkw, qks, qkb, relb);
    k_good<<<256, 256>>>();
    k_attn<<<dim3(NWIN, NCLS), 256, SM_ATTN>>>(x, qkw, qks, qkb, relb, wvw, wvs, wvb);
    dim3 cg(16, 64, NCLS);
    k_conv3<3><<<cg, 256, SM_C3>>>(0, 1, mmsw, mmss, mmsb, 0);
    k_conv3<2><<<cg, 256, SM_C2>>>(1, 2, mmsw, mmss, mmsb, 3);
    k_final<<<cg, 256, SM_FIN>>>(mmsw, mmss, mmsb, catw, cats, catb, out);
}